// round 6
// baseline (speedup 1.0000x reference)
#include <cuda_runtime.h>
#include <cstdint>

// Problem constants
#define BATCH 8
#define C_IN  64
#define H_IN  128
#define W_IN  128
#define OCH   64
#define KK    9      // 3x3 taps
#define HOUT  128
#define WOUT  128
#define PIX   (HOUT*WOUT)   // 16384 per batch

// ---------------- scratch (static device globals; no allocation) -----------
__device__ __align__(16) float g_nhwc[BATCH * H_IN * W_IN * C_IN];  // 33.5 MB
// Weight fragments, per-lane layout for mma.m16n8k16 B operand.
// [k][ntG(8)][kstep(4)][lane(32)]
__device__ __align__(16) uint4 g_wfAB[KK * 8 * 4 * 32];  // {h0,h1,l0,l1}
__device__ __align__(16) uint2 g_wfH [KK * 8 * 4 * 32];  // {h0,h1}

// ---------------- helpers ----------------------------------------------------
__device__ __forceinline__ unsigned short f2bf(float x) {
    unsigned short u;
    asm("cvt.rn.bf16.f32 %0, %1;" : "=h"(u) : "f"(x));
    return u;
}
__device__ __forceinline__ float bf2f(unsigned short u) {
    return __uint_as_float(((unsigned)u) << 16);
}
__device__ __forceinline__ uint32_t packbf(float lo, float hi) {
    uint32_t d;
    asm("cvt.rn.bf16x2.f32 %0, %1, %2;" : "=r"(d) : "f"(hi), "f"(lo));
    return d;
}
__device__ __forceinline__ uint32_t smem_u32(const void* p) {
    uint32_t a;
    asm("{ .reg .u64 t; cvta.to.shared.u64 t, %1; cvt.u32.u64 %0, t; }" : "=r"(a) : "l"(p));
    return a;
}
__device__ __forceinline__ void ldmA(uint32_t* a, uint32_t addr) {
    asm volatile("ldmatrix.sync.aligned.m8n8.x4.shared.b16 {%0,%1,%2,%3}, [%4];"
                 : "=r"(a[0]), "=r"(a[1]), "=r"(a[2]), "=r"(a[3]) : "r"(addr));
}
__device__ __forceinline__ void mma_bf16(float* c, const uint32_t* a,
                                         uint32_t b0, uint32_t b1) {
    asm volatile(
        "mma.sync.aligned.m16n8k16.row.col.f32.bf16.bf16.f32 "
        "{%0,%1,%2,%3}, {%4,%5,%6,%7}, {%8,%9}, {%0,%1,%2,%3};"
        : "+f"(c[0]), "+f"(c[1]), "+f"(c[2]), "+f"(c[3])
        : "r"(a[0]), "r"(a[1]), "r"(a[2]), "r"(a[3]), "r"(b0), "r"(b1));
}

// ---------------- Kernel A1: NCHW -> NHWC transpose ------------------------
__global__ void k_transpose(const float* __restrict__ in) {
    __shared__ float tile[32][33];
    int bh = blockIdx.z;
    int b  = bh / H_IN;
    int y  = bh % H_IN;
    int xBase = blockIdx.x * 32;
    int cBase = blockIdx.y * 32;
    int tx = threadIdx.x;
    int ty = threadIdx.y;
#pragma unroll
    for (int i = 0; i < 32; i += 8) {
        int c = cBase + ty + i;
        tile[ty + i][tx] = in[(((size_t)b * C_IN + c) * H_IN + y) * W_IN + xBase + tx];
    }
    __syncthreads();
#pragma unroll
    for (int i = 0; i < 32; i += 8) {
        int x = xBase + ty + i;
        g_nhwc[(((size_t)b * H_IN + y) * W_IN + x) * C_IN + cBase + tx] = tile[tx][ty + i];
    }
}

// ---------------- Kernel A2: weight -> per-lane MMA fragments ----------------
// B[ch][oc] for tap k = weight[oc][ch][k/3][k%3]. Fragment mapping (m16n8k16 B):
//   lane: n = nt*8 + (lane>>2); kk0 = kstep*16 + (lane&3)*2
//   b0 = {B[kk0][n], B[kk0+1][n]}, b1 = {B[kk0+8][n], B[kk0+9][n]}
__global__ void k_wtrans(const float* __restrict__ w) {
    int idx = blockIdx.x * 256 + threadIdx.x;
    if (idx >= KK * 8 * 4 * 32) return;
    int lane  = idx & 31;
    int kstep = (idx >> 5) & 3;
    int ntG   = (idx >> 7) & 7;
    int k     = idx >> 10;
    int n   = ntG * 8 + (lane >> 2);
    int kk0 = kstep * 16 + (lane & 3) * 2;

    float w00 = w[((size_t)n * C_IN + kk0)     * KK + k];
    float w01 = w[((size_t)n * C_IN + kk0 + 1) * KK + k];
    float w10 = w[((size_t)n * C_IN + kk0 + 8) * KK + k];
    float w11 = w[((size_t)n * C_IN + kk0 + 9) * KK + k];

    unsigned short h00 = f2bf(w00), h01 = f2bf(w01), h10 = f2bf(w10), h11 = f2bf(w11);
    uint32_t h0 = (uint32_t)h00 | ((uint32_t)h01 << 16);
    uint32_t h1 = (uint32_t)h10 | ((uint32_t)h11 << 16);
    uint32_t l0 = (uint32_t)f2bf(w00 - bf2f(h00)) | ((uint32_t)f2bf(w01 - bf2f(h01)) << 16);
    uint32_t l1 = (uint32_t)f2bf(w10 - bf2f(h10)) | ((uint32_t)f2bf(w11 - bf2f(h11)) << 16);

    g_wfAB[idx] = make_uint4(h0, h1, l0, l1);
    g_wfH[idx]  = make_uint2(h0, h1);
}

// ---------------- Kernel B: fused deformable-sample + bf16 MMA GEMM ---------
// Block: 128 px (M) x 64 oc (N), 256 threads / 8 warps.
// Warp tile: 32 px x 32 oc = 2 m-tiles x 4 n-tiles of m16n8k16.
// 3-product split: acc += Ahi*Bhi + Ahi*Blo + Alo*Bhi.
#define A_STRIDE 144   // bytes per px row in smem (72 bf16; conflict-free ldmatrix)

__global__ void __launch_bounds__(256, 2) k_fused(const float* __restrict__ offset,
                                                  const float* __restrict__ mask,
                                                  const float* __restrict__ bias,
                                                  float* __restrict__ out) {
    __shared__ __align__(16) unsigned char sA[128 * A_STRIDE];  // 18 KB bf16 tile

    int tid = threadIdx.x;
    int blk = blockIdx.x;
    int ho  = blk & (HOUT - 1);
    int b   = blk >> 7;
    int pBase = ho * WOUT;

    int px   = tid >> 1;            // 0..127
    int half = tid & 1;             // channel half (32 ch each)
    int p    = pBase + px;

    int wid  = tid >> 5;
    int lane = tid & 31;
    int wpx  = wid & 3;             // px group (32 px)
    int woc  = wid >> 2;            // oc group (32 oc)

    // ldmatrix source addresses (x4): rows (l&7) + 8*((l>>3)&1), col-block l>>4
    int lr = (lane & 7) + ((lane >> 3) & 1) * 8;
    int cb = lane >> 4;
    uint32_t aBase = smem_u32(sA);
    uint32_t lm0 = aBase + (uint32_t)(wpx * 32 + lr) * A_STRIDE + cb * 16;
    uint32_t lm1 = lm0 + 16 * A_STRIDE;

    float acc[2][4][4];
#pragma unroll
    for (int i = 0; i < 2; i++)
#pragma unroll
        for (int j = 0; j < 4; j++)
#pragma unroll
            for (int q = 0; q < 4; q++) acc[i][j][q] = 0.f;

    const float* nhwcB = g_nhwc + (size_t)b * H_IN * W_IN * C_IN + half * 32;
    const float* offB  = offset + (size_t)b * 2 * KK * PIX;
    const float* mskB  = mask   + (size_t)b * KK * PIX;
    unsigned char* sRow = sA + px * A_STRIDE + half * 64;

    for (int k = 0; k < KK; k++) {
        // ---- per-pixel bilinear params ----
        float py  = (float)(k / 3 + ho - 1) + offB[(size_t)(2 * k) * PIX + p];
        float pxx = (float)(k % 3 + px - 1) + offB[(size_t)(2 * k + 1) * PIX + p];
        float m   = mskB[(size_t)k * PIX + p];
        float y0f = floorf(py), x0f = floorf(pxx);
        int   y0 = (int)y0f, x0 = (int)x0f;
        float wy1 = py - y0f, wx1 = pxx - x0f;
        float wy0 = 1.f - wy1, wx0 = 1.f - wx1;
        float cw[4]; int cof[4];
#pragma unroll
        for (int c2 = 0; c2 < 4; c2++) {
            int cy = c2 >> 1, cx = c2 & 1;
            int yy = y0 + cy, xx = x0 + cx;
            bool vld = (yy >= 0) & (yy < H_IN) & (xx >= 0) & (xx < W_IN);
            float w = (cy ? wy1 : wy0) * (cx ? wx1 : wx0) * m;
            cw[c2] = vld ? w : 0.f;
            int yc = min(max(yy, 0), H_IN - 1);
            int xc = min(max(xx, 0), W_IN - 1);
            cof[c2] = (yc * W_IN + xc) * C_IN;
        }

        // ---- gather + interpolate 32 channels (fp32) ----
        float v[32];
#pragma unroll
        for (int j = 0; j < 32; j++) v[j] = 0.f;
#pragma unroll
        for (int c2 = 0; c2 < 4; c2++) {
            float w = cw[c2];
            const float4* src = (const float4*)(nhwcB + cof[c2]);
#pragma unroll
            for (int j = 0; j < 8; j++) {
                float4 t = src[j];
                v[j * 4 + 0] += w * t.x; v[j * 4 + 1] += w * t.y;
                v[j * 4 + 2] += w * t.z; v[j * 4 + 3] += w * t.w;
            }
        }

        // ---- bf16 split ----
        uint32_t hiP[16], loP[16];
#pragma unroll
        for (int j = 0; j < 16; j++) {
            hiP[j] = packbf(v[2 * j], v[2 * j + 1]);
            float hl = __uint_as_float(hiP[j] << 16);
            float hh = __uint_as_float(hiP[j] & 0xFFFF0000u);
            loP[j] = packbf(v[2 * j] - hl, v[2 * j + 1] - hh);
        }

        __syncthreads();   // previous tap's MMA done reading sA
        // ---- store A_hi ----
#pragma unroll
        for (int jj = 0; jj < 4; jj++)
            *(uint4*)(sRow + jj * 16) = make_uint4(hiP[4 * jj], hiP[4 * jj + 1],
                                                   hiP[4 * jj + 2], hiP[4 * jj + 3]);
        __syncthreads();

        // ---- phase A: Ahi x Bhi + Ahi x Blo ----
#pragma unroll
        for (int ks = 0; ks < 4; ks++) {
            uint32_t a0[4], a1[4];
            ldmA(a0, lm0 + ks * 32);
            ldmA(a1, lm1 + ks * 32);
#pragma unroll
            for (int nt = 0; nt < 4; nt++) {
                uint4 bq = g_wfAB[(((k * 8) + woc * 4 + nt) * 4 + ks) * 32 + lane];
                mma_bf16(acc[0][nt], a0, bq.x, bq.y);
                mma_bf16(acc[1][nt], a1, bq.x, bq.y);
                mma_bf16(acc[0][nt], a0, bq.z, bq.w);
                mma_bf16(acc[1][nt], a1, bq.z, bq.w);
            }
        }

        __syncthreads();
        // ---- store A_lo ----
#pragma unroll
        for (int jj = 0; jj < 4; jj++)
            *(uint4*)(sRow + jj * 16) = make_uint4(loP[4 * jj], loP[4 * jj + 1],
                                                   loP[4 * jj + 2], loP[4 * jj + 3]);
        __syncthreads();

        // ---- phase B: Alo x Bhi ----
#pragma unroll
        for (int ks = 0; ks < 4; ks++) {
            uint32_t a0[4], a1[4];
            ldmA(a0, lm0 + ks * 32);
            ldmA(a1, lm1 + ks * 32);
#pragma unroll
            for (int nt = 0; nt < 4; nt++) {
                uint2 bh = g_wfH[(((k * 8) + woc * 4 + nt) * 4 + ks) * 32 + lane];
                mma_bf16(acc[0][nt], a0, bh.x, bh.y);
                mma_bf16(acc[1][nt], a1, bh.x, bh.y);
            }
        }
    }

    // ---- epilogue: bias + store ----
    // Fragment D: lane g=lane>>2, tig=lane&3: rows g,g+8 (px), cols 2tig,2tig+1 (oc)
    int g   = lane >> 2;
    int tig = lane & 3;
#pragma unroll
    for (int mt = 0; mt < 2; mt++) {
#pragma unroll
        for (int nt = 0; nt < 4; nt++) {
            int px0 = wpx * 32 + mt * 16 + g;
            int oc0 = woc * 32 + nt * 8 + tig * 2;
            float b0 = bias[oc0], b1 = bias[oc0 + 1];
            float* o0 = out + ((size_t)(b * OCH + oc0)) * PIX + pBase;
            float* o1 = o0 + PIX;
            o0[px0]     = acc[mt][nt][0] + b0;
            o1[px0]     = acc[mt][nt][1] + b1;
            o0[px0 + 8] = acc[mt][nt][2] + b0;
            o1[px0 + 8] = acc[mt][nt][3] + b1;
        }
    }
}

// ---------------- launch ----------------------------------------------------
extern "C" void kernel_launch(void* const* d_in, const int* in_sizes, int n_in,
                              void* d_out, int out_size) {
    const float* input  = (const float*)d_in[0];
    const float* offset = (const float*)d_in[1];
    const float* mask   = (const float*)d_in[2];
    const float* weight = (const float*)d_in[3];
    const float* bias   = (const float*)d_in[4];
    float* out = (float*)d_out;

    dim3 tb(32, 8);
    dim3 tg(W_IN / 32, C_IN / 32, BATCH * H_IN);
    k_transpose<<<tg, tb>>>(input);
    k_wtrans<<<(KK * 8 * 4 * 32 + 255) / 256, 256>>>(weight);
    k_fused<<<BATCH * HOUT, 256>>>(offset, mask, bias, out);
}